// round 17
// baseline (speedup 1.0000x reference)
#include <cuda_runtime.h>
#include <cuda_bf16.h>
#include <cstdint>

#define BB 256
#define NN 512
#define DD 6
#define FF 128
#define MAXDEG 6
#define BN (BB * NN)
#define TM 128
#define SSTR 136               // S/W smem row stride in bf16 (128+8); 272B
#define G_PER_DEG 24
#define FUSED_CTAS (G_PER_DEG * MAXDEG)   // 144

// ---- smem byte offsets ----
#define SM_WH    0                         // 128 x SSTR bf16 = 34816B
#define SM_WL    34816                     // -> 69632
#define SM_S     69632                     // 2 buffers x (SH+SL = 69632B)
#define SBUFB    69632                     // bytes per S buffer (hi at 0, lo at +34816)
#define SM_NODE  208896                    // 2 x 128 ints = 1024B
#define SM_BIAS  209920                    // 128 floats
#define SM_BYTES 210432

// ---- device scratch ----
__device__ int g_list[MAXDEG * BN];
__device__ int g_cnt[MAXDEG];
__device__ __nv_bfloat16 g_wh[MAXDEG * FF * FF];   // W^T hi: [d][n][k]
__device__ __nv_bfloat16 g_wl[MAXDEG * FF * FF];

__device__ __forceinline__ uint32_t smem_u32(const void* p) {
    uint32_t a;
    asm("{ .reg .u64 t; cvta.to.shared.u64 t, %1; cvt.u32.u64 %0, t; }" : "=r"(a) : "l"(p));
    return a;
}
__device__ __forceinline__ void cpa16(uint32_t dst, const void* src) {
    asm volatile("cp.async.cg.shared.global [%0], [%1], 16;" :: "r"(dst), "l"(src));
}
#define CPA_COMMIT() asm volatile("cp.async.commit_group;" ::: "memory")
#define CPA_WAIT0()  asm volatile("cp.async.wait_group 0;" ::: "memory")
#define BAR_SYNC(id)   asm volatile("bar.sync %0, 384;"   :: "r"(id) : "memory")
#define BAR_ARRIVE(id) asm volatile("bar.arrive %0, 384;" :: "r"(id) : "memory")

__device__ __forceinline__ void ldm_x4(uint32_t& r0, uint32_t& r1, uint32_t& r2, uint32_t& r3,
                                       uint32_t addr) {
    asm volatile("ldmatrix.sync.aligned.m8n8.x4.shared.b16 {%0,%1,%2,%3}, [%4];"
                 : "=r"(r0), "=r"(r1), "=r"(r2), "=r"(r3) : "r"(addr));
}
__device__ __forceinline__ void mma16816(float* c, const uint32_t* a, uint32_t b0, uint32_t b1) {
    asm volatile("mma.sync.aligned.m16n8k16.row.col.f32.bf16.bf16.f32 "
                 "{%0,%1,%2,%3}, {%4,%5,%6,%7}, {%8,%9}, {%0,%1,%2,%3};"
                 : "+f"(c[0]), "+f"(c[1]), "+f"(c[2]), "+f"(c[3])
                 : "r"(a[0]), "r"(a[1]), "r"(a[2]), "r"(a[3]), "r"(b0), "r"(b1));
}
__device__ __forceinline__ void split2(float v0, float v1, uint32_t& hp, uint32_t& lp) {
    __nv_bfloat16 h0 = __float2bfloat16(v0);
    __nv_bfloat16 h1 = __float2bfloat16(v1);
    __nv_bfloat16 l0 = __float2bfloat16(v0 - __bfloat162float(h0));
    __nv_bfloat16 l1 = __float2bfloat16(v1 - __bfloat162float(h1));
    hp = ((uint32_t)__bfloat16_as_ushort(h1) << 16) | __bfloat16_as_ushort(h0);
    lp = ((uint32_t)__bfloat16_as_ushort(l1) << 16) | __bfloat16_as_ushort(l0);
}

// ===================== kernel 1: bucket + W split (fused) ==========
__global__ void k_prep(const int* __restrict__ edges, const float* __restrict__ W) {
    int t = threadIdx.x;                 // 512 threads
    if (blockIdx.x < 256) {
        __shared__ int c[MAXDEG];
        __shared__ int base[MAXDEG];
        if (t < MAXDEG) c[t] = 0;
        __syncthreads();
        int node = blockIdx.x * 512 + t;
        int deg = 0;
#pragma unroll
        for (int s = 0; s < DD; s++) deg += (edges[node * DD + s] >= 0);
        if (deg >= MAXDEG) deg = MAXDEG - 1;
        int pos = atomicAdd(&c[deg], 1);
        __syncthreads();
        if (t < MAXDEG) base[t] = atomicAdd(&g_cnt[t], c[t]);
        __syncthreads();
        g_list[deg * BN + base[deg] + pos] = node;
    } else {
        int i = (blockIdx.x - 256) * 512 + t;          // < 98304
        int d = i >> 14, rem = i & 16383, k = rem >> 7, n = rem & 127;
        float v = W[i];                                 // W[d][k][n]
        __nv_bfloat16 hi = __float2bfloat16(v);
        float lo = v - __bfloat162float(hi);
        int o = (d << 14) + (n << 7) + k;               // W^T[d][n][k]
        g_wh[o] = hi;
        g_wl[o] = __float2bfloat16(lo);
    }
}

// ===================== kernel 2: fused producer/consumer ===========
// 144 persistent CTAs (24 per degree), 384 threads.
// Warps 0-7: HMMA consumers (32x64 warp tiles). Warps 8-11: gather producers.
// Double-buffered full 128x128 S tiles (hi+lo). Named barriers:
//   full[b]  = id 1+b (producers arrive, consumers sync)
//   empty[b] = id 3+b (consumers arrive, producers sync)
__global__ __launch_bounds__(384, 1)
void k_fused(const float* __restrict__ atoms, const int* __restrict__ edges,
             const float* __restrict__ bias, float* __restrict__ out) {
    const int d = blockIdx.x / G_PER_DEG;
    const int rank = blockIdx.x % G_PER_DEG;
    int ps_d = 0, cnt = 0;
#pragma unroll
    for (int t = 0; t < MAXDEG; t++) {
        int c = g_cnt[t];
        if (t < d) ps_d += (c + 127) & ~127;
        if (t == d) cnt = c;
    }
    const int ntiles = (cnt + 127) >> 7;
    if (rank >= ntiles) return;
    const int pe = ps_d + cnt;

    extern __shared__ char smc[];
    const uint32_t sb = smem_u32(smc);
    const int tid = threadIdx.x, wid = tid >> 5, lid = tid & 31;
    int*   snode = (int*)(smc + SM_NODE);
    float* sbias = (float*)(smc + SM_BIAS);
    if (tid < TM) sbias[tid] = bias[d * FF + tid];

    // ---- stage W hi/lo once (all threads)
    const char* whp = (const char*)(g_wh + (d << 14));
    const char* wlp = (const char*)(g_wl + (d << 14));
    for (int i = tid; i < FF * 16; i += 384) {
        int row = i >> 4, ch = (i & 15) * 16;
        uint32_t dsto = (uint32_t)row * (SSTR * 2) + ch;
        cpa16(sb + SM_WH + dsto, whp + row * 256 + ch);
        cpa16(sb + SM_WL + dsto, wlp + row * 256 + ch);
    }
    CPA_COMMIT();
    CPA_WAIT0();
    __syncthreads();

    if (wid >= 8) {
        // ================= PRODUCER (4 warps, 128 threads) =================
        const int wg = tid - 256;            // 0..127
        const int rr = wg >> 2;              // row within 32-row pass
        const int c0 = (wg & 3) * 32;        // col base (32 floats)
        const int li = d * BN;
        int iter = 0;
        for (int m = rank; m < ntiles; m += G_PER_DEG, iter++) {
            const int b = iter & 1;
            if (iter >= 2) BAR_SYNC(3 + b);
            const uint32_t bufH = sb + SM_S + (uint32_t)b * SBUFB;
            const uint32_t bufL = bufH + 34816;
#pragma unroll
            for (int p = 0; p < 4; p++) {
                const int r = p * 32 + rr;
                int i = m * TM + r;
                i = (i < cnt) ? i : cnt - 1;
                const int node = g_list[li + i];
                if ((wg & 3) == 0) snode[b * TM + r] = node;
                const float4* Ap = (const float4*)atoms + (size_t)node * 32 + (c0 >> 2);
                float4 a[8];
#pragma unroll
                for (int j = 0; j < 8; j++) a[j] = Ap[j];
                const int nb = (node >> 9) << 9;
                const int eb = node * DD;
#pragma unroll
                for (int s = 0; s < DD; s++) {
                    int e = edges[eb + s];
                    if (e >= 0) {
                        e = (e < NN) ? e : 0;
                        const float4* Np = (const float4*)atoms + (size_t)(nb + e) * 32 + (c0 >> 2);
#pragma unroll
                        for (int j = 0; j < 8; j++) {
                            float4 v = Np[j];
                            a[j].x += v.x; a[j].y += v.y; a[j].z += v.z; a[j].w += v.w;
                        }
                    }
                }
                const uint32_t rowb = (uint32_t)r * (SSTR * 2) + c0 * 2;
#pragma unroll
                for (int j = 0; j < 8; j++) {
                    uint32_t hp0, lp0, hp1, lp1;
                    split2(a[j].x, a[j].y, hp0, lp0);
                    split2(a[j].z, a[j].w, hp1, lp1);
                    uint2 hv = make_uint2(hp0, hp1), lv = make_uint2(lp0, lp1);
                    *(uint2*)(smc + (bufH - sb) + rowb + 8 * j) = hv;
                    *(uint2*)(smc + (bufL - sb) + rowb + 8 * j) = lv;
                }
            }
            BAR_ARRIVE(1 + b);
        }
    } else {
        // ================= CONSUMER (8 warps, 256 threads) =================
        const int rg = wid & 3, cg = wid >> 2;
        const uint32_t alo = (uint32_t)((lid & 15) * (SSTR * 2) + ((lid >> 4) & 1) * 16);
        const uint32_t arow0 = (uint32_t)(rg * 32) * (SSTR * 2);
        const int bnl = (lid & 7) + ((lid >> 4) & 1) * 8;
        const int bk  = ((lid >> 3) & 1) * 8;
        const int cb  = (lid & 3) * 2;
        int iter = 0;
        for (int m = rank; m < ntiles; m += G_PER_DEG, iter++) {
            const int b = iter & 1;
            BAR_SYNC(1 + b);
            const uint32_t bufH = sb + SM_S + (uint32_t)b * SBUFB;
            const uint32_t bufL = bufH + 34816;

            float acc[16][4];
#pragma unroll
            for (int t = 0; t < 16; t++)
#pragma unroll
                for (int q = 0; q < 4; q++) acc[t][q] = 0.f;

#pragma unroll
            for (int kb = 0; kb < 8; kb++) {
                const uint32_t ak = (uint32_t)kb * 32;
                const uint32_t wk = (uint32_t)((kb * 16 + bk) * 2);
                uint32_t ah0[4], ah1[4], al0[4], al1[4];
                ldm_x4(ah0[0], ah0[1], ah0[2], ah0[3], bufH + arow0 + alo + ak);
                ldm_x4(ah1[0], ah1[1], ah1[2], ah1[3], bufH + arow0 + 16 * (SSTR * 2) + alo + ak);
                ldm_x4(al0[0], al0[1], al0[2], al0[3], bufL + arow0 + alo + ak);
                ldm_x4(al1[0], al1[1], al1[2], al1[3], bufL + arow0 + 16 * (SSTR * 2) + alo + ak);
#pragma unroll
                for (int p = 0; p < 4; p++) {
                    const uint32_t boff = (uint32_t)((cg * 64 + p * 16 + bnl) * (SSTR * 2)) + wk;
                    uint32_t bh0, bh1, bh2, bh3, bl0, bl1, bl2, bl3;
                    ldm_x4(bh0, bh1, bh2, bh3, sb + SM_WH + boff);
                    ldm_x4(bl0, bl1, bl2, bl3, sb + SM_WL + boff);
                    float* a00 = acc[p * 2];
                    float* a01 = acc[p * 2 + 1];
                    float* a10 = acc[8 + p * 2];
                    float* a11 = acc[8 + p * 2 + 1];
                    mma16816(a00, ah0, bh0, bh1);
                    mma16816(a01, ah0, bh2, bh3);
                    mma16816(a10, ah1, bh0, bh1);
                    mma16816(a11, ah1, bh2, bh3);
                    mma16816(a00, ah0, bl0, bl1);
                    mma16816(a01, ah0, bl2, bl3);
                    mma16816(a10, ah1, bl0, bl1);
                    mma16816(a11, ah1, bl2, bl3);
                    mma16816(a00, al0, bh0, bh1);
                    mma16816(a01, al0, bh2, bh3);
                    mma16816(a10, al1, bh0, bh1);
                    mma16816(a11, al1, bh2, bh3);
                }
            }

            // ---- epilogue: bias + relu + scatter
            const int tb = ps_d + m * TM;
#pragma unroll
            for (int half = 0; half < 2; half++) {
                int r0 = rg * 32 + half * 16 + (lid >> 2);
                int r1 = r0 + 8;
                bool ok0 = (tb + r0) < pe;
                bool ok1 = (tb + r1) < pe;
                float* op0 = out + (size_t)snode[b * TM + r0] * FF;
                float* op1 = out + (size_t)snode[b * TM + r1] * FF;
#pragma unroll
                for (int p = 0; p < 4; p++) {
#pragma unroll
                    for (int j = 0; j < 2; j++) {
                        int cc = cg * 64 + p * 16 + j * 8 + cb;
                        float b0 = sbias[cc], b1 = sbias[cc + 1];
                        float* a = acc[half * 8 + p * 2 + j];
                        if (ok0) {
                            float x0 = fmaxf(a[0] + b0, 0.f);
                            float x1 = fmaxf(a[1] + b1, 0.f);
                            *(float2*)(op0 + cc) = make_float2(x0, x1);
                        }
                        if (ok1) {
                            float x2 = fmaxf(a[2] + b0, 0.f);
                            float x3 = fmaxf(a[3] + b1, 0.f);
                            *(float2*)(op1 + cc) = make_float2(x2, x3);
                        }
                    }
                }
            }
            BAR_ARRIVE(3 + b);
        }
    }
}

// ===================== launch =====================
extern "C" void kernel_launch(void* const* d_in, const int* in_sizes, int n_in,
                              void* d_out, int out_size) {
    const float* atoms = (const float*)d_in[0];
    const int*   edges = (const int*)d_in[1];
    const float* W     = (const float*)d_in[2];
    const float* bias  = (const float*)d_in[3];
    float*       out   = (float*)d_out;

    cudaFuncSetAttribute(k_fused, cudaFuncAttributeMaxDynamicSharedMemorySize, SM_BYTES);

    void* cnt_ptr = nullptr;
    cudaGetSymbolAddress(&cnt_ptr, g_cnt);
    cudaMemsetAsync(cnt_ptr, 0, MAXDEG * sizeof(int));

    k_prep<<<448, 512>>>(edges, W);
    k_fused<<<FUSED_CTAS, 384, SM_BYTES>>>(atoms, edges, bias, out);
}